// round 2
// baseline (speedup 1.0000x reference)
#include <cuda_runtime.h>
#include <cstdint>

// Problem constants (fixed by the reference)
#define BB 8
#define TT 512
#define DD 512
#define MAX_LEN 7680   // TT * 15

// Scratch: per-batch inclusive cumsum of clamped durations.
// 8*512*4 = 16 KB, static device global (no allocation).
__device__ int g_cum[BB * TT];

// ---------------------------------------------------------------------------
// Kernel 1: inclusive scan of max(durations,1) per batch row.
// One block per batch, 512 threads, Hillis-Steele in shared memory.
// ---------------------------------------------------------------------------
__global__ void scan_kernel(const int* __restrict__ dur) {
    __shared__ int s[TT];
    const int b = blockIdx.x;
    const int t = threadIdx.x;
    int v = dur[b * TT + t];
    v = (v < 1) ? 1 : v;
    s[t] = v;
    __syncthreads();
#pragma unroll
    for (int off = 1; off < TT; off <<= 1) {
        int x = (t >= off) ? s[t - off] : 0;
        __syncthreads();
        s[t] += x;
        __syncthreads();
    }
    g_cum[b * TT + t] = s[t];
}

// ---------------------------------------------------------------------------
// Kernel 2: length regulation (gather-expand).
// Block: 128 x 4 threads. Each y-slice handles one output frame:
//   frame n of batch b -> source phoneme idx = searchsorted_right(cum, n)
//   128 threads copy 128 float4 (512 floats, 2 KB) coalesced.
// Frames beyond the valid length are zero-filled.
// Grid: (MAX_LEN/4, BB).
// ---------------------------------------------------------------------------
__global__ void __launch_bounds__(512) expand_kernel(
    const float* __restrict__ feat,   // (B, T, D)
    float4* __restrict__ out)         // (B, MAX_LEN, D) as float4
{
    const int b   = blockIdx.y;
    const int n   = blockIdx.x * 4 + threadIdx.y;   // output frame within batch
    const int tid = threadIdx.x;                    // 0..127 -> float4 lane

    const int* __restrict__ cum = g_cum + b * TT;
    const int total = __ldg(&cum[TT - 1]);

    float4* dst = out + ((size_t)b * MAX_LEN + n) * (DD / 4) + tid;

    if (n >= total) {
        *dst = make_float4(0.f, 0.f, 0.f, 0.f);
        return;
    }

    // searchsorted(cum, n, side="right"): first i with cum[i] > n.
    // 9 iterations; loads are warp-uniform -> L1 broadcast hits.
    int lo = 0, hi = TT;
    while (lo < hi) {
        int mid = (lo + hi) >> 1;
        if (__ldg(&cum[mid]) <= n) lo = mid + 1;
        else                       hi = mid;
    }
    // n < total == cum[TT-1] guarantees lo <= TT-1 (matches jnp.minimum clamp).

    const float4* src =
        (const float4*)(feat + ((size_t)b * TT + lo) * DD) + tid;
    *dst = __ldg(src);
}

// ---------------------------------------------------------------------------
// Launch
// ---------------------------------------------------------------------------
extern "C" void kernel_launch(void* const* d_in, const int* in_sizes, int n_in,
                              void* d_out, int out_size) {
    const float* feat = (const float*)d_in[0];   // features (8,512,512) f32
    const int*   dur  = (const int*)d_in[1];     // durations (8,512) i32
    float4*      out  = (float4*)d_out;          // (8,7680,512) f32

    (void)in_sizes; (void)n_in; (void)out_size;

    scan_kernel<<<BB, TT>>>(dur);

    dim3 block(128, 4, 1);
    dim3 grid(MAX_LEN / 4, BB, 1);
    expand_kernel<<<grid, block>>>(feat, out);
}

// round 3
// speedup vs baseline: 1.5987x; 1.5987x over previous
#include <cuda_runtime.h>
#include <cstdint>

// Problem constants (fixed by the reference)
#define BB 8
#define TT 512
#define DD 512
#define D4 (DD / 4)      // 128 float4 per frame
#define MAX_LEN 7680     // TT * 15

// Scratch (static device globals; no allocation):
// g_idx[b][n] = source phoneme for output frame n, or -1 for zero-pad.
__device__ int g_idx[BB * MAX_LEN];

// ---------------------------------------------------------------------------
// Kernel 1: scan + scatter-fill of the frame->phoneme index table.
// One block per batch, 512 threads.
//   - Hillis-Steele inclusive cumsum of max(dur,1) in shared memory
//   - thread t scatters value t into g_idx[b][cum[t]-dur .. cum[t])
//   - tail [total, MAX_LEN) filled with -1
// ---------------------------------------------------------------------------
__global__ void scan_fill_kernel(const int* __restrict__ dur) {
    __shared__ int s[TT];
    const int b = blockIdx.x;
    const int t = threadIdx.x;

    int v = dur[b * TT + t];
    v = (v < 1) ? 1 : v;
    s[t] = v;
    __syncthreads();
#pragma unroll
    for (int off = 1; off < TT; off <<= 1) {
        int x = (t >= off) ? s[t - off] : 0;
        __syncthreads();
        s[t] += x;
        __syncthreads();
    }
    const int end   = s[t];        // inclusive cumsum
    const int start = end - v;
    const int total = s[TT - 1];   // valid after the scan's final barrier

    int* __restrict__ row = g_idx + b * MAX_LEN;
    for (int i = start; i < end; i++) row[i] = t;          // <= 15 stores
    for (int i = total + t; i < MAX_LEN; i += TT) row[i] = -1;
}

// ---------------------------------------------------------------------------
// Kernel 2: pure gather-expand.
// Block (128, 4) = 512 threads; each block covers 16 output frames of one
// batch. Thread (x=lane, y) handles frames base+y+{0,4,8,12} — 4 independent
// float4 load/store pairs (MLP=4), 64 B of output per thread.
// Grid: (MAX_LEN/16, BB).
// ---------------------------------------------------------------------------
__global__ void __launch_bounds__(512) expand_kernel(
    const float4* __restrict__ feat,  // (B, T, D/4)
    float4* __restrict__ out)         // (B, MAX_LEN, D/4)
{
    const int b    = blockIdx.y;
    const int base = blockIdx.x * 16 + threadIdx.y;  // frames base + 4*j
    const int lane = threadIdx.x;                    // 0..127

    const int* __restrict__ row = g_idx + b * MAX_LEN;
    const float4* __restrict__ fb = feat + (size_t)b * TT * D4;
    float4* __restrict__ ob = out + ((size_t)b * MAX_LEN + base) * D4 + lane;

    int idx[4];
#pragma unroll
    for (int j = 0; j < 4; j++)
        idx[j] = __ldg(&row[base + 4 * j]);          // warp-uniform broadcasts

    float4 val[4];
    const float4 zero = make_float4(0.f, 0.f, 0.f, 0.f);
#pragma unroll
    for (int j = 0; j < 4; j++)
        val[j] = (idx[j] >= 0) ? __ldg(fb + (size_t)idx[j] * D4 + lane) : zero;

#pragma unroll
    for (int j = 0; j < 4; j++)
        ob[(size_t)4 * j * D4] = val[j];
}

// ---------------------------------------------------------------------------
// Launch
// ---------------------------------------------------------------------------
extern "C" void kernel_launch(void* const* d_in, const int* in_sizes, int n_in,
                              void* d_out, int out_size) {
    const float4* feat = (const float4*)d_in[0];  // features (8,512,512) f32
    const int*    dur  = (const int*)d_in[1];     // durations (8,512) i32
    float4*       out  = (float4*)d_out;          // (8,7680,512) f32

    (void)in_sizes; (void)n_in; (void)out_size;

    scan_fill_kernel<<<BB, TT>>>(dur);

    dim3 block(128, 4, 1);
    dim3 grid(MAX_LEN / 16, BB, 1);
    expand_kernel<<<grid, block>>>(feat, out);
}